// round 1
// baseline (speedup 1.0000x reference)
#include <cuda_runtime.h>
#include <math.h>

#define B_   64
#define S_   512
#define H_   1024
#define M_   (B_ * S_)      // 32768
#define TWOH 2048

#define BM 128
#define BN 128
#define BK 16
#define NBLK (H_ / BN)      // 8 N-tiles

// ---- scratch (no allocations allowed) ----
__device__ float g_d[B_ * H_];        // d[b,h] = dec[b,:] . W_h[h,0:H]
__device__ float g_part[NBLK * M_];   // per-N-tile partial scores
__device__ float g_atmp[M_];          // softmax(axis=0)*mask, pre-row-norm

// ------------------------------------------------------------------
// Kernel 1: d[b,h] = sum_k dec[b,k] * W[h,k]   (W row-major [H, 2H])
// grid (H/256, B), 256 threads
// ------------------------------------------------------------------
__global__ void k_dproj(const float* __restrict__ dec,
                        const float* __restrict__ W)
{
    int b = blockIdx.y;
    int h = blockIdx.x * 256 + threadIdx.x;
    __shared__ float sd[H_];
    for (int i = threadIdx.x; i < H_; i += 256) sd[i] = dec[b * H_ + i];
    __syncthreads();

    const float4* w4 = (const float4*)(W + (size_t)h * TWOH);
    float acc = 0.f;
#pragma unroll 8
    for (int k4 = 0; k4 < H_ / 4; k4++) {
        float4 w = w4[k4];
        acc += w.x * sd[4 * k4 + 0] + w.y * sd[4 * k4 + 1]
             + w.z * sd[4 * k4 + 2] + w.w * sd[4 * k4 + 3];
    }
    g_d[b * H_ + h] = acc;
}

// ------------------------------------------------------------------
// Kernel 2: fused GEMM + tanh + v-reduction.
// C[m,n] = sum_k enc[m,k] * W[n, H+k];  partial[m] += tanh(C + d[b,n]) * v[n]
// grid (NBLK, M/BM), 256 threads, 8x8 register tiles.
// ------------------------------------------------------------------
__global__ __launch_bounds__(256)
void k_gemm_fused(const float* __restrict__ A,     // enc as [M_, H_]
                  const float* __restrict__ W,     // [H_, 2H]
                  const float* __restrict__ v)
{
    __shared__ float As[BK][BM];
    __shared__ float Bs[BK][BN];
    __shared__ float red[16][BM];
    __shared__ float dsh[BN];
    __shared__ float vsh[BN];

    const int tid = threadIdx.x;
    const int tx = tid & 15;       // n direction
    const int ty = tid >> 4;       // m direction
    const int m0 = blockIdx.y * BM;
    const int n0 = blockIdx.x * BN;
    const int b  = m0 >> 9;        // 512 rows per batch, BM divides S_

    if (tid < BN) {
        dsh[tid] = g_d[b * H_ + n0 + tid];
        vsh[tid] = v[n0 + tid];
    }

    float acc[8][8];
#pragma unroll
    for (int i = 0; i < 8; i++)
#pragma unroll
        for (int j = 0; j < 8; j++) acc[i][j] = 0.f;

    const float4* A4 = (const float4*)A;   // ld = 256 float4
    const float4* W4 = (const float4*)W;   // ld = 512 float4

    for (int kt = 0; kt < H_; kt += BK) {
        const int k4base = kt >> 2;
#pragma unroll
        for (int q = 0; q < 2; q++) {
            int idx = tid + q * 256;           // 0..511
            int row = idx >> 2;                // 0..127
            int kq  = idx & 3;                 // float4 within BK
            float4 fa = A4[(size_t)(m0 + row) * (H_ / 4) + k4base + kq];
            As[kq * 4 + 0][row] = fa.x;
            As[kq * 4 + 1][row] = fa.y;
            As[kq * 4 + 2][row] = fa.z;
            As[kq * 4 + 3][row] = fa.w;
            float4 fb = W4[(size_t)(n0 + row) * (TWOH / 4) + (H_ / 4) + k4base + kq];
            Bs[kq * 4 + 0][row] = fb.x;
            Bs[kq * 4 + 1][row] = fb.y;
            Bs[kq * 4 + 2][row] = fb.z;
            Bs[kq * 4 + 3][row] = fb.w;
        }
        __syncthreads();
#pragma unroll
        for (int k = 0; k < BK; k++) {
            float a[8], bb[8];
#pragma unroll
            for (int i = 0; i < 8; i++) a[i] = As[k][ty * 8 + i];
#pragma unroll
            for (int j = 0; j < 8; j++) bb[j] = Bs[k][tx * 8 + j];
#pragma unroll
            for (int i = 0; i < 8; i++)
#pragma unroll
                for (int j = 0; j < 8; j++) acc[i][j] += a[i] * bb[j];
        }
        __syncthreads();
    }

    // epilogue: tanh + dot with v over this block's 128 n-columns
#pragma unroll
    for (int i = 0; i < 8; i++) {
        float s = 0.f;
#pragma unroll
        for (int j = 0; j < 8; j++) {
            int n = tx * 8 + j;
            s += tanhf(acc[i][j] + dsh[n]) * vsh[n];
        }
        red[tx][ty * 8 + i] = s;
    }
    __syncthreads();
    if (tid < BM) {
        float s = 0.f;
#pragma unroll
        for (int t = 0; t < 16; t++) s += red[t][tid];
        g_part[(size_t)blockIdx.x * M_ + m0 + tid] = s;
    }
}

// ------------------------------------------------------------------
// Kernel 3: scores -> softmax over batch dim (axis 0) per s, * mask
// grid S_, 64 threads (one per b)
// ------------------------------------------------------------------
__global__ void k_softmax_b(const float* __restrict__ mask)
{
    int s = blockIdx.x;
    int b = threadIdx.x;

    float val = 0.f;
#pragma unroll
    for (int p = 0; p < NBLK; p++) val += g_part[p * M_ + b * S_ + s];

    __shared__ float wmax[2], wsum[2];
    float mx = val;
#pragma unroll
    for (int o = 16; o; o >>= 1) mx = fmaxf(mx, __shfl_xor_sync(0xffffffffu, mx, o));
    if ((b & 31) == 0) wmax[b >> 5] = mx;
    __syncthreads();
    mx = fmaxf(wmax[0], wmax[1]);

    float e = expf(val - mx);
    float sum = e;
#pragma unroll
    for (int o = 16; o; o >>= 1) sum += __shfl_xor_sync(0xffffffffu, sum, o);
    if ((b & 31) == 0) wsum[b >> 5] = sum;
    __syncthreads();
    sum = wsum[0] + wsum[1];

    g_atmp[b * S_ + s] = (e / sum) * mask[s * B_ + b];
}

// ------------------------------------------------------------------
// Kernel 4: per-b renormalize over s; writes final a into out[0:M_]
// grid B_, 512 threads (one per s)
// ------------------------------------------------------------------
__global__ void k_norm(float* __restrict__ out)
{
    int b = blockIdx.x;
    int t = threadIdx.x;
    float val = g_atmp[b * S_ + t];

    float s = val;
#pragma unroll
    for (int o = 16; o; o >>= 1) s += __shfl_xor_sync(0xffffffffu, s, o);
    __shared__ float ws[16];
    if ((t & 31) == 0) ws[t >> 5] = s;
    __syncthreads();
    if (t < 32) {
        float x = (t < 16) ? ws[t] : 0.f;
#pragma unroll
        for (int o = 16; o; o >>= 1) x += __shfl_xor_sync(0xffffffffu, x, o);
        if (t == 0) ws[0] = x;
    }
    __syncthreads();
    out[b * S_ + t] = val / (ws[0] + 1e-10f);
}

// ------------------------------------------------------------------
// Kernel 5: context[b,h] = sum_s a[b,s] * enc[b,s,h]
// grid (H/256, B), 256 threads; reads a from out[0:M_]
// ------------------------------------------------------------------
__global__ void k_context(const float* __restrict__ enc,
                          const float* __restrict__ a,
                          float* __restrict__ ctx)
{
    int b = blockIdx.y;
    int h = blockIdx.x * 256 + threadIdx.x;
    __shared__ float ash[S_];
    for (int i = threadIdx.x; i < S_; i += 256) ash[i] = a[b * S_ + i];
    __syncthreads();

    const float* e = enc + (size_t)b * S_ * H_ + h;
    float acc = 0.f;
#pragma unroll 4
    for (int s = 0; s < S_; s++) acc += ash[s] * e[(size_t)s * H_];
    ctx[b * H_ + h] = acc;
}

// ------------------------------------------------------------------
extern "C" void kernel_launch(void* const* d_in, const int* in_sizes, int n_in,
                              void* d_out, int out_size)
{
    const float* enc  = (const float*)d_in[0];  // [B,S,H]
    const float* dec  = (const float*)d_in[1];  // [B,H]
    const float* mask = (const float*)d_in[2];  // [S,B]
    const float* W    = (const float*)d_in[3];  // [H,2H]
    const float* v    = (const float*)d_in[4];  // [H]
    float* out = (float*)d_out;                 // a [B,1,S] then context [B,1,H]

    k_dproj<<<dim3(H_ / 256, B_), 256>>>(dec, W);
    k_gemm_fused<<<dim3(NBLK, M_ / BM), 256>>>(enc, W, v);
    k_softmax_b<<<S_, B_>>>(mask);
    k_norm<<<B_, S_>>>(out);
    k_context<<<dim3(H_ / 256, B_), 256>>>(enc, out, out + M_);
}

// round 3
// speedup vs baseline: 3.7769x; 3.7769x over previous
#include <cuda_runtime.h>
#include <cuda_bf16.h>
#include <math.h>
#include <stdint.h>

#define B_   64
#define S_   512
#define H_   1024
#define M_   (B_ * S_)      // 32768
#define TWOH 2048

#define BM 128
#define BN 256
#define BK 64               // bf16 elements per k-step
#define NSTEP 48            // 3 segments * 16 steps
#define NBLK (H_ / BN)      // 4 n-tiles
#define THREADS 512
#define STAGES 3
#define A_BYTES (BM * BK * 2)          // 16384
#define B_BYTES (BN * BK * 2)          // 32768
#define STAGE_BYTES (A_BYTES + B_BYTES) // 49152
#define DSMEM (STAGES * STAGE_BYTES)

#define SW128(o) ((o) ^ (((o) >> 3) & 0x70))

// ---------------- scratch ----------------
__device__ float g_d[B_ * H_];
__device__ float g_part[NBLK * M_];
__device__ float g_atmp[M_];
__device__ __nv_bfloat16 g_ah[(size_t)M_ * H_];
__device__ __nv_bfloat16 g_al[(size_t)M_ * H_];
__device__ __nv_bfloat16 g_bh[(size_t)H_ * H_];
__device__ __nv_bfloat16 g_bl[(size_t)H_ * H_];

// ---------------- helpers ----------------
__device__ __forceinline__ uint32_t smem_u32(const void* p) {
    uint32_t a;
    asm("{ .reg .u64 t; cvta.to.shared.u64 t, %1; cvt.u32.u64 %0, t; }"
        : "=r"(a) : "l"(p));
    return a;
}
__device__ __forceinline__ void cp_async16(uint32_t s, const void* g) {
    asm volatile("cp.async.cg.shared.global [%0], [%1], 16;" :: "r"(s), "l"(g) : "memory");
}
__device__ __forceinline__ void ldsm4(uint32_t* r, uint32_t a) {
    asm volatile("ldmatrix.sync.aligned.m8n8.x4.shared.b16 {%0,%1,%2,%3}, [%4];"
                 : "=r"(r[0]), "=r"(r[1]), "=r"(r[2]), "=r"(r[3]) : "r"(a));
}
__device__ __forceinline__ void mma16816(float* c, const uint32_t* a,
                                         uint32_t b0, uint32_t b1) {
    asm volatile(
        "mma.sync.aligned.m16n8k16.row.col.f32.bf16.bf16.f32 "
        "{%0,%1,%2,%3}, {%4,%5,%6,%7}, {%8,%9}, {%0,%1,%2,%3};"
        : "+f"(c[0]), "+f"(c[1]), "+f"(c[2]), "+f"(c[3])
        : "r"(a[0]), "r"(a[1]), "r"(a[2]), "r"(a[3]), "r"(b0), "r"(b1));
}

// ------------------------------------------------------------------
// fp32 -> bf16 hi/lo split, enc
// ------------------------------------------------------------------
__global__ void k_conv_enc(const float* __restrict__ x)
{
    size_t i = ((size_t)blockIdx.x * 256 + threadIdx.x) * 4;
    float4 f = *(const float4*)(x + i);
    __nv_bfloat16 h0 = __float2bfloat16_rn(f.x);
    __nv_bfloat16 h1 = __float2bfloat16_rn(f.y);
    __nv_bfloat16 h2 = __float2bfloat16_rn(f.z);
    __nv_bfloat16 h3 = __float2bfloat16_rn(f.w);
    __nv_bfloat16 l0 = __float2bfloat16_rn(f.x - __bfloat162float(h0));
    __nv_bfloat16 l1 = __float2bfloat16_rn(f.y - __bfloat162float(h1));
    __nv_bfloat16 l2 = __float2bfloat16_rn(f.z - __bfloat162float(h2));
    __nv_bfloat16 l3 = __float2bfloat16_rn(f.w - __bfloat162float(h3));
    *(__nv_bfloat162*)(g_ah + i)     = __nv_bfloat162(h0, h1);
    *(__nv_bfloat162*)(g_ah + i + 2) = __nv_bfloat162(h2, h3);
    *(__nv_bfloat162*)(g_al + i)     = __nv_bfloat162(l0, l1);
    *(__nv_bfloat162*)(g_al + i + 2) = __nv_bfloat162(l2, l3);
}

// ------------------------------------------------------------------
// fp32 -> bf16 hi/lo split, W second half (cols H..2H), as [n][k]
// ------------------------------------------------------------------
__global__ void k_conv_w(const float* __restrict__ W)
{
    size_t i = ((size_t)blockIdx.x * 256 + threadIdx.x) * 4;
    size_t n = i >> 10;
    size_t k = i & 1023;
    float4 f = *(const float4*)(W + n * TWOH + H_ + k);
    __nv_bfloat16 h0 = __float2bfloat16_rn(f.x);
    __nv_bfloat16 h1 = __float2bfloat16_rn(f.y);
    __nv_bfloat16 h2 = __float2bfloat16_rn(f.z);
    __nv_bfloat16 h3 = __float2bfloat16_rn(f.w);
    __nv_bfloat16 l0 = __float2bfloat16_rn(f.x - __bfloat162float(h0));
    __nv_bfloat16 l1 = __float2bfloat16_rn(f.y - __bfloat162float(h1));
    __nv_bfloat16 l2 = __float2bfloat16_rn(f.z - __bfloat162float(h2));
    __nv_bfloat16 l3 = __float2bfloat16_rn(f.w - __bfloat162float(h3));
    *(__nv_bfloat162*)(g_bh + i)     = __nv_bfloat162(h0, h1);
    *(__nv_bfloat162*)(g_bh + i + 2) = __nv_bfloat162(h2, h3);
    *(__nv_bfloat162*)(g_bl + i)     = __nv_bfloat162(l0, l1);
    *(__nv_bfloat162*)(g_bl + i + 2) = __nv_bfloat162(l2, l3);
}

// ------------------------------------------------------------------
// d[b,h] = dec[b,:] . W[h, 0:H]
// ------------------------------------------------------------------
__global__ void k_dproj(const float* __restrict__ dec, const float* __restrict__ W)
{
    int b = blockIdx.y;
    int h = blockIdx.x * 256 + threadIdx.x;
    __shared__ float sd[H_];
    for (int i = threadIdx.x; i < H_; i += 256) sd[i] = dec[b * H_ + i];
    __syncthreads();
    const float4* w4 = (const float4*)(W + (size_t)h * TWOH);
    float acc = 0.f;
#pragma unroll 8
    for (int k4 = 0; k4 < H_ / 4; k4++) {
        float4 w = w4[k4];
        acc += w.x * sd[4 * k4] + w.y * sd[4 * k4 + 1] + w.z * sd[4 * k4 + 2] + w.w * sd[4 * k4 + 3];
    }
    g_d[b * H_ + h] = acc;
}

// ------------------------------------------------------------------
// HMMA GEMM (mma.sync bf16, hi/lo split over packed K=3072)
// + fused tanh(.+d).v reduction into g_part[nblk][m]
// ------------------------------------------------------------------
__global__ void __launch_bounds__(THREADS, 1)
k_gemm(const float* __restrict__ v)
{
    extern __shared__ char smem[];
    const uint32_t sbase = smem_u32(smem);

    __shared__ float dsh[BN], vsh[BN];
    __shared__ float red[4][BM];

    const int tid = threadIdx.x;
    const int lane = tid & 31;
    const int wid = tid >> 5;
    const int warp_m = wid & 3;       // 4 warps along M (32 rows each)
    const int warp_n = wid >> 2;      // 4 warps along N (64 cols each)
    const int m0 = blockIdx.y * BM;
    const int n0 = blockIdx.x * BN;
    const int b  = m0 >> 9;

    if (tid < BN) {
        dsh[tid] = g_d[b * H_ + n0 + tid];
        vsh[tid] = v[n0 + tid];
    }

    float acc[2][8][4];
#pragma unroll
    for (int i = 0; i < 2; i++)
#pragma unroll
        for (int j = 0; j < 8; j++)
#pragma unroll
            for (int q = 0; q < 4; q++) acc[i][j][q] = 0.f;

    auto prefetch = [&](int step) {
        const int stage = step % STAGES;
        const int seg = step >> 4;
        const int kkl = (step & 15) * BK;
        const __nv_bfloat16* Asrc = (seg == 1) ? g_al : g_ah;
        const __nv_bfloat16* Bsrc = (seg == 2) ? g_bl : g_bh;
        const uint32_t sA = sbase + stage * STAGE_BYTES;
        const uint32_t sB = sA + A_BYTES;
#pragma unroll
        for (int i = 0; i < 2; i++) {
            int idx = tid + i * THREADS;          // 0..1023
            int row = idx >> 3, c16 = idx & 7;
            cp_async16(sA + SW128(row * 128 + c16 * 16),
                       Asrc + (size_t)(m0 + row) * H_ + kkl + c16 * 8);
        }
#pragma unroll
        for (int i = 0; i < 4; i++) {
            int idx = tid + i * THREADS;          // 0..2047
            int row = idx >> 3, c16 = idx & 7;
            cp_async16(sB + SW128(row * 128 + c16 * 16),
                       Bsrc + (size_t)(n0 + row) * H_ + kkl + c16 * 8);
        }
        asm volatile("cp.async.commit_group;" ::: "memory");
    };

    prefetch(0);
    prefetch(1);

    for (int step = 0; step < NSTEP; step++) {
        asm volatile("cp.async.wait_group 1;" ::: "memory");
        __syncthreads();
        if (step + 2 < NSTEP) prefetch(step + 2);

        const int stage = step % STAGES;
        const uint32_t sA = sbase + stage * STAGE_BYTES;
        const uint32_t sB = sA + A_BYTES;
#pragma unroll
        for (int k16 = 0; k16 < 4; k16++) {
            uint32_t a[2][4];
            const int kc = k16 * 16 + (lane >> 4) * 8;
#pragma unroll
            for (int i = 0; i < 2; i++) {
                int mr = warp_m * 32 + i * 16 + ((lane >> 3) & 1) * 8 + (lane & 7);
                ldsm4(a[i], sA + SW128(mr * 128 + kc * 2));
            }
#pragma unroll
            for (int jp = 0; jp < 4; jp++) {
                int nr = warp_n * 64 + jp * 16 + ((lane >> 3) & 1) * 8 + (lane & 7);
                uint32_t br[4];
                ldsm4(br, sB + SW128(nr * 128 + kc * 2));
#pragma unroll
                for (int i = 0; i < 2; i++) {
                    mma16816(acc[i][2 * jp],     a[i], br[0], br[2]);
                    mma16816(acc[i][2 * jp + 1], a[i], br[1], br[3]);
                }
            }
        }
    }
    asm volatile("cp.async.wait_group 0;" ::: "memory");
    __syncthreads();

    // epilogue: tanh(C + d) . v over this tile's 256 n-columns
#pragma unroll
    for (int i = 0; i < 2; i++) {
        float r0 = 0.f, r1 = 0.f;
#pragma unroll
        for (int j = 0; j < 8; j++) {
            int n = warp_n * 64 + j * 8 + (lane & 3) * 2;
            r0 += tanhf(acc[i][j][0] + dsh[n]) * vsh[n]
                + tanhf(acc[i][j][1] + dsh[n + 1]) * vsh[n + 1];
            r1 += tanhf(acc[i][j][2] + dsh[n]) * vsh[n]
                + tanhf(acc[i][j][3] + dsh[n + 1]) * vsh[n + 1];
        }
        r0 += __shfl_xor_sync(0xffffffffu, r0, 1);
        r0 += __shfl_xor_sync(0xffffffffu, r0, 2);
        r1 += __shfl_xor_sync(0xffffffffu, r1, 1);
        r1 += __shfl_xor_sync(0xffffffffu, r1, 2);
        if ((lane & 3) == 0) {
            int mloc = warp_m * 32 + i * 16 + (lane >> 2);
            red[warp_n][mloc]     = r0;
            red[warp_n][mloc + 8] = r1;
        }
    }
    __syncthreads();
    if (tid < BM) {
        float s = red[0][tid] + red[1][tid] + red[2][tid] + red[3][tid];
        g_part[(size_t)blockIdx.x * M_ + m0 + tid] = s;
    }
}

// ------------------------------------------------------------------
// softmax over batch dim (axis 0) per s, * mask
// ------------------------------------------------------------------
__global__ void k_softmax_b(const float* __restrict__ mask)
{
    int s = blockIdx.x;
    int b = threadIdx.x;
    float val = 0.f;
#pragma unroll
    for (int p = 0; p < NBLK; p++) val += g_part[(size_t)p * M_ + b * S_ + s];

    __shared__ float wmax[2], wsum[2];
    float mx = val;
#pragma unroll
    for (int o = 16; o; o >>= 1) mx = fmaxf(mx, __shfl_xor_sync(0xffffffffu, mx, o));
    if ((b & 31) == 0) wmax[b >> 5] = mx;
    __syncthreads();
    mx = fmaxf(wmax[0], wmax[1]);

    float e = expf(val - mx);
    float sum = e;
#pragma unroll
    for (int o = 16; o; o >>= 1) sum += __shfl_xor_sync(0xffffffffu, sum, o);
    if ((b & 31) == 0) wsum[b >> 5] = sum;
    __syncthreads();
    sum = wsum[0] + wsum[1];

    g_atmp[b * S_ + s] = (e / sum) * mask[s * B_ + b];
}

// ------------------------------------------------------------------
// per-b renormalize over s
// ------------------------------------------------------------------
__global__ void k_norm(float* __restrict__ out)
{
    int b = blockIdx.x;
    int t = threadIdx.x;
    float val = g_atmp[b * S_ + t];
    float s = val;
#pragma unroll
    for (int o = 16; o; o >>= 1) s += __shfl_xor_sync(0xffffffffu, s, o);
    __shared__ float ws[16];
    if ((t & 31) == 0) ws[t >> 5] = s;
    __syncthreads();
    if (t < 32) {
        float x = (t < 16) ? ws[t] : 0.f;
#pragma unroll
        for (int o = 16; o; o >>= 1) x += __shfl_xor_sync(0xffffffffu, x, o);
        if (t == 0) ws[0] = x;
    }
    __syncthreads();
    out[b * S_ + t] = val / (ws[0] + 1e-10f);
}

// ------------------------------------------------------------------
// context[b,h] = sum_s a[b,s] * enc[b,s,h]
// ------------------------------------------------------------------
__global__ void k_context(const float* __restrict__ enc,
                          const float* __restrict__ a,
                          float* __restrict__ ctx)
{
    int b = blockIdx.y;
    int h = blockIdx.x * 256 + threadIdx.x;
    __shared__ float ash[S_];
    for (int i = threadIdx.x; i < S_; i += 256) ash[i] = a[b * S_ + i];
    __syncthreads();
    const float* e = enc + (size_t)b * S_ * H_ + h;
    float acc = 0.f;
#pragma unroll 4
    for (int s = 0; s < S_; s++) acc += ash[s] * e[(size_t)s * H_];
    ctx[b * H_ + h] = acc;
}

// ------------------------------------------------------------------
extern "C" void kernel_launch(void* const* d_in, const int* in_sizes, int n_in,
                              void* d_out, int out_size)
{
    const float* enc  = (const float*)d_in[0];  // [B,S,H]
    const float* dec  = (const float*)d_in[1];  // [B,H]
    const float* mask = (const float*)d_in[2];  // [S,B]
    const float* W    = (const float*)d_in[3];  // [H,2H]
    const float* v    = (const float*)d_in[4];  // [H]
    float* out = (float*)d_out;                 // a [B,1,S] then context [B,1,H]

    cudaFuncSetAttribute(k_gemm, cudaFuncAttributeMaxDynamicSharedMemorySize, DSMEM);

    k_conv_enc<<<(size_t)M_ * H_ / 1024, 256>>>(enc);
    k_conv_w<<<(size_t)H_ * H_ / 1024, 256>>>(W);
    k_dproj<<<dim3(H_ / 256, B_), 256>>>(dec, W);
    k_gemm<<<dim3(NBLK, M_ / BM), THREADS, DSMEM>>>(v);
    k_softmax_b<<<S_, B_>>>(mask);
    k_norm<<<B_, S_>>>(out);
    k_context<<<dim3(H_ / 256, B_), 256>>>(enc, out, out + M_);
}